// round 15
// baseline (speedup 1.0000x reference)
#include <cuda_runtime.h>
#include <math_constants.h>

// RMAC: x [64,512,32,32] fp32 -> out [64,512,1,1]
// Row/col ranges (H=W=32, L=3): R0=[0,32) R1=[0,21) R2=[11,32) R3=[0,16) R4=[8,24) R5=[16,32)
// 14 regions: (R0,R0) w=2 (global + l=1), 2x2 over {R1,R2}, 3x3 over {R3,R4,R5}.
// out[b,c] = sum_r w_r * M[b,r,c] / (sqrt(SS[b,r]) + 1e-6)
//
// Stage1 is now a PERSISTENT 1-wave grid (1184 blocks = 8 per SM), grid-stride
// over the 8192 4-map groups: block start cost + wave transitions paid once
// instead of ~7x. Stage2: PDL secondary (unchanged, measured-floor ~5us).

#define NREG  14
#define NGRP  8192     // 4-map groups
#define GRID1 1184     // 148 SMs x 8 resident blocks

__device__ float g_M[64 * NREG * 512];   // [b][r][ch]
__device__ float g_SS[64 * NREG];        // region sums of squares (RED atomics);
                                         // zero at load, re-zeroed by stage2.

struct __align__(16) SmemT {
    float s2[4][6][36];     // [warp][range][col] (pad 36) — warp-private
    float ssq[2][4][16];    // [iter parity][warp][region] — double-buffered
};

__device__ __forceinline__ float4 f4max(float4 a, float4 b) {
    return make_float4(fmaxf(a.x, b.x), fmaxf(a.y, b.y), fmaxf(a.z, b.z), fmaxf(a.w, b.w));
}
__device__ __forceinline__ float4 shflx4(float4 v, int m) {
    float4 r;
    r.x = __shfl_xor_sync(0xffffffffu, v.x, m);
    r.y = __shfl_xor_sync(0xffffffffu, v.y, m);
    r.z = __shfl_xor_sync(0xffffffffu, v.z, m);
    r.w = __shfl_xor_sync(0xffffffffu, v.w, m);
    return r;
}

// Warp per (b,c) map. Lane l: q = l>>3 (row phase), c0 = l&7 (4-col group).
// float4 k covers row 4k+q, cols 4c0..4c0+3. 8x LDG.128 fully coalesced.
__global__ __launch_bounds__(128, 8) void rmac_stage1(const float* __restrict__ x) {
    __shared__ SmemT sm;
    const int tid  = threadIdx.x;
    const int w    = tid >> 5;
    const int lane = tid & 31;
    const int q    = lane >> 3;
    const int c0   = lane & 7;

    int it = 0;
    for (int grp = blockIdx.x; grp < NGRP; grp += GRID1, ++it) {
        const int par = it & 1;
        const int wid = grp * 4 + w;          // (b,c) map index

        const float4* __restrict__ p = (const float4*)x + (size_t)wid * 256 + lane;

        float4 v0 = __ldcs(p +   0), v1 = __ldcs(p +  32);
        float4 v2 = __ldcs(p +  64), v3 = __ldcs(p +  96);
        float4 v4 = __ldcs(p + 128), v5 = __ldcs(p + 160);
        float4 v6 = __ldcs(p + 192), v7 = __ldcs(p + 224);

        float4 pc = f4max(v2, v3);                 // rows [8,16)
        float4 pd = f4max(v4, v5);                 // rows [16,24)
        float4 g3 = f4max(f4max(v0, v1), pc);      // rows [0,16)
        float4 g5 = f4max(pd, f4max(v6, v7));      // rows [16,32)
        float4 pb = (q == 3) ? pc : v3;            // rows [11,16): row 11 = k2,q3
        float4 pa = (q == 0) ? pd : v4;            // rows [16,21): row 20 = k5,q0

        float4 m0 = f4max(g3, g5);   // [0,32)
        float4 m1 = f4max(g3, pa);   // [0,21)
        float4 m2 = f4max(pb, g5);   // [11,32)
        float4 m3 = g3;              // [0,16)
        float4 m4 = f4max(pc, pd);   // [8,24)
        float4 m5 = g5;              // [16,32)

        // Butterfly over row-phase q (lane bits 3,4): full column maxes everywhere.
        m0 = f4max(m0, shflx4(m0, 8)); m0 = f4max(m0, shflx4(m0, 16));
        m1 = f4max(m1, shflx4(m1, 8)); m1 = f4max(m1, shflx4(m1, 16));
        m2 = f4max(m2, shflx4(m2, 8)); m2 = f4max(m2, shflx4(m2, 16));
        m3 = f4max(m3, shflx4(m3, 8)); m3 = f4max(m3, shflx4(m3, 16));
        m4 = f4max(m4, shflx4(m4, 8)); m4 = f4max(m4, shflx4(m4, 16));
        m5 = f4max(m5, shflx4(m5, 8)); m5 = f4max(m5, shflx4(m5, 16));

        // s2 is warp-private: __syncwarp below guards both publish and the
        // previous iteration's reads (same warp).
        __syncwarp();
        if (q == 0) {   // lanes 0..7 publish col maxes (c0 == lane)
            *(float4*)&sm.s2[w][0][c0 << 2] = m0;
            *(float4*)&sm.s2[w][1][c0 << 2] = m1;
            *(float4*)&sm.s2[w][2][c0 << 2] = m2;
            *(float4*)&sm.s2[w][3][c0 << 2] = m3;
            *(float4*)&sm.s2[w][4][c0 << 2] = m4;
            *(float4*)&sm.s2[w][5][c0 << 2] = m5;
        }
        __syncwarp();

        if (lane < NREG) {
            int R, Cc;
            if (lane == 0)     { R = 0; Cc = 0; }
            else if (lane < 5) { R = 1 + ((lane - 1) >> 1); Cc = 1 + ((lane - 1) & 1); }
            else               { int t = lane - 5; R = 3 + t / 3; Cc = 3 + t % 3; }
            const int cs = (Cc == 2) ? 11 : (Cc == 4) ? 8 : (Cc == 5) ? 16 : 0;
            const int ce = (Cc == 1) ? 21 : (Cc == 3) ? 16 : (Cc == 4) ? 24 : 32;
            float mm = -CUDART_INF_F;
            for (int j = cs; j < ce; ++j)
                mm = fmaxf(mm, sm.s2[w][R][j]);
            const int b = wid >> 9, ch = wid & 511;
            g_M[(b * NREG + lane) * 512 + ch] = mm;
            sm.ssq[par][w][lane] = mm * mm;
        }
        __syncthreads();   // ssq[par] complete; also releases prior parity buffer

        if (tid < NREG) {  // return-unused -> RED (no-return), 896 spread addrs
            const int b = grp >> 7;    // 128 groups per batch
            float t = sm.ssq[par][0][tid] + sm.ssq[par][1][tid] +
                      sm.ssq[par][2][tid] + sm.ssq[par][3][tid];
            atomicAdd(&g_SS[b * NREG + tid], t);
        }
        // other warps may run ahead into parity ^1 — safe (double buffer).
    }

    asm volatile("griddepcontrol.launch_dependents;");
}

// PDL secondary: scheduled while stage1 drains; HW-waits for grid completion.
__global__ __launch_bounds__(256) void rmac_stage2(float* __restrict__ out) {
    const int b   = blockIdx.x >> 1;
    const int ch  = ((blockIdx.x & 1) << 8) + threadIdx.x;
    const int tid = threadIdx.x;

    __shared__ float s_inv[NREG];

    asm volatile("griddepcontrol.wait;" ::: "memory");

    // issue all 14 independent g_M loads first (overlap with norm chain below)
    const float* __restrict__ base = g_M + b * NREG * 512 + ch;
    float v[NREG];
#pragma unroll
    for (int r = 0; r < NREG; ++r)
        v[r] = base[r * 512];

    if (tid < NREG)
        s_inv[tid] = 1.0f / (sqrtf(g_SS[b * NREG + tid]) + 1e-6f);
    __syncthreads();
    if (tid < NREG)                  // re-zero off the critical path
        g_SS[b * NREG + tid] = 0.0f;

    float acc = 2.0f * v[0] * s_inv[0];     // (R0,R0) weight 2
#pragma unroll
    for (int r = 1; r < NREG; ++r)
        acc += v[r] * s_inv[r];
    out[b * 512 + ch] = acc;
}

extern "C" void kernel_launch(void* const* d_in, const int* in_sizes, int n_in,
                              void* d_out, int out_size) {
    const float* x = (const float*)d_in[0];
    float* out = (float*)d_out;

    rmac_stage1<<<GRID1, 128>>>(x);   // persistent 1-wave grid

    cudaLaunchConfig_t cfg = {};
    cfg.gridDim  = dim3(128, 1, 1);
    cfg.blockDim = dim3(256, 1, 1);
    cfg.dynamicSmemBytes = 0;
    cfg.stream = 0;
    cudaLaunchAttribute attr[1];
    attr[0].id = cudaLaunchAttributeProgrammaticStreamSerialization;
    attr[0].val.programmaticStreamSerializationAllowed = 1;
    cfg.attrs = attr;
    cfg.numAttrs = 1;
    cudaLaunchKernelEx(&cfg, rmac_stage2, out);
}

// round 16
// speedup vs baseline: 1.0947x; 1.0947x over previous
#include <cuda_runtime.h>
#include <math_constants.h>

// RMAC: x [64,512,32,32] fp32 -> out [64,512,1,1]
// Row/col ranges (H=W=32, L=3): R0=[0,32) R1=[0,21) R2=[11,32) R3=[0,16) R4=[8,24) R5=[16,32)
// 14 regions: (R0,R0) w=2 (global + l=1), 2x2 over {R1,R2}, 3x3 over {R3,R4,R5}.
// out[b,c] = sum_r w_r * M[b,r,c] / (sqrt(SS[b,r]) + 1e-6)
//
// Two kernels. PDL with launch_dependents at BLOCK START (R9/R14 had it at block
// end, which delays the dependent launch to grid completion and hides nothing):
// trigger now fires when the last wave begins, overlapping stage2's ramp with
// stage1's tail. griddepcontrol.wait still guarantees full completion+visibility.

#define NREG 14

__device__ float g_M[64 * NREG * 512];   // [b][r][ch]
__device__ float g_SS[64 * NREG];        // region sums of squares (RED atomics);
                                         // zero at load, re-zeroed by stage2.

struct __align__(16) SmemT {
    float s2[4][6][36];    // [warp][range][col] (pad 36)
    float ssq[4][16];      // per-warp region squares
};

__device__ __forceinline__ float4 f4max(float4 a, float4 b) {
    return make_float4(fmaxf(a.x, b.x), fmaxf(a.y, b.y), fmaxf(a.z, b.z), fmaxf(a.w, b.w));
}
__device__ __forceinline__ float4 shflx4(float4 v, int m) {
    float4 r;
    r.x = __shfl_xor_sync(0xffffffffu, v.x, m);
    r.y = __shfl_xor_sync(0xffffffffu, v.y, m);
    r.z = __shfl_xor_sync(0xffffffffu, v.z, m);
    r.w = __shfl_xor_sync(0xffffffffu, v.w, m);
    return r;
}

// Warp per (b,c) map. Lane l: q = l>>3 (row phase), c0 = l&7 (4-col group).
// float4 k covers row 4k+q, cols 4c0..4c0+3. 8x LDG.128 fully coalesced.
__global__ __launch_bounds__(128, 8) void rmac_stage1(const float* __restrict__ x) {
    __shared__ SmemT sm;
    const int tid  = threadIdx.x;
    const int w    = tid >> 5;
    const int lane = tid & 31;
    const int wid  = blockIdx.x * 4 + w;      // (b,c) map index
    const int q    = lane >> 3;
    const int c0   = lane & 7;

    // Fire the PDL trigger immediately: dependent grid may launch once every
    // primary CTA has executed this (i.e., when the last wave STARTS).
    asm volatile("griddepcontrol.launch_dependents;");

    const float4* __restrict__ p = (const float4*)x + (size_t)wid * 256 + lane;

    float4 v0 = __ldcs(p +   0), v1 = __ldcs(p +  32);
    float4 v2 = __ldcs(p +  64), v3 = __ldcs(p +  96);
    float4 v4 = __ldcs(p + 128), v5 = __ldcs(p + 160);
    float4 v6 = __ldcs(p + 192), v7 = __ldcs(p + 224);

    float4 pc = f4max(v2, v3);                 // rows [8,16)
    float4 pd = f4max(v4, v5);                 // rows [16,24)
    float4 g3 = f4max(f4max(v0, v1), pc);      // rows [0,16)
    float4 g5 = f4max(pd, f4max(v6, v7));      // rows [16,32)
    float4 pb = (q == 3) ? pc : v3;            // rows [11,16): row 11 = k2,q3
    float4 pa = (q == 0) ? pd : v4;            // rows [16,21): row 20 = k5,q0

    float4 m0 = f4max(g3, g5);   // [0,32)
    float4 m1 = f4max(g3, pa);   // [0,21)
    float4 m2 = f4max(pb, g5);   // [11,32)
    float4 m3 = g3;              // [0,16)
    float4 m4 = f4max(pc, pd);   // [8,24)
    float4 m5 = g5;              // [16,32)

    // Butterfly over row-phase q (lane bits 3,4): full column maxes in all lanes.
    m0 = f4max(m0, shflx4(m0, 8)); m0 = f4max(m0, shflx4(m0, 16));
    m1 = f4max(m1, shflx4(m1, 8)); m1 = f4max(m1, shflx4(m1, 16));
    m2 = f4max(m2, shflx4(m2, 8)); m2 = f4max(m2, shflx4(m2, 16));
    m3 = f4max(m3, shflx4(m3, 8)); m3 = f4max(m3, shflx4(m3, 16));
    m4 = f4max(m4, shflx4(m4, 8)); m4 = f4max(m4, shflx4(m4, 16));
    m5 = f4max(m5, shflx4(m5, 8)); m5 = f4max(m5, shflx4(m5, 16));

    if (q == 0) {   // lanes 0..7 publish col maxes (c0 == lane)
        *(float4*)&sm.s2[w][0][c0 << 2] = m0;
        *(float4*)&sm.s2[w][1][c0 << 2] = m1;
        *(float4*)&sm.s2[w][2][c0 << 2] = m2;
        *(float4*)&sm.s2[w][3][c0 << 2] = m3;
        *(float4*)&sm.s2[w][4][c0 << 2] = m4;
        *(float4*)&sm.s2[w][5][c0 << 2] = m5;
    }
    __syncwarp();

    if (lane < NREG) {
        int R, Cc;
        if (lane == 0)     { R = 0; Cc = 0; }
        else if (lane < 5) { R = 1 + ((lane - 1) >> 1); Cc = 1 + ((lane - 1) & 1); }
        else               { int t = lane - 5; R = 3 + t / 3; Cc = 3 + t % 3; }
        const int cs = (Cc == 2) ? 11 : (Cc == 4) ? 8 : (Cc == 5) ? 16 : 0;
        const int ce = (Cc == 1) ? 21 : (Cc == 3) ? 16 : (Cc == 4) ? 24 : 32;
        float mm = -CUDART_INF_F;
        for (int j = cs; j < ce; ++j)
            mm = fmaxf(mm, sm.s2[w][R][j]);
        const int b = wid >> 9, ch = wid & 511;
        g_M[(b * NREG + lane) * 512 + ch] = mm;
        sm.ssq[w][lane] = mm * mm;
    }
    __syncthreads();

    if (tid < NREG) {   // return-unused -> RED (no-return), 896 spread addresses
        const int b = blockIdx.x >> 7;
        float t = sm.ssq[0][tid] + sm.ssq[1][tid] + sm.ssq[2][tid] + sm.ssq[3][tid];
        atomicAdd(&g_SS[b * NREG + tid], t);
    }
}

// PDL secondary: blocks scheduled while stage1's last wave runs; prelude done
// before the HW-sleep wait; wait releases at primary completion + visibility.
__global__ __launch_bounds__(256) void rmac_stage2(float* __restrict__ out) {
    const int b   = blockIdx.x >> 1;
    const int ch  = ((blockIdx.x & 1) << 8) + threadIdx.x;
    const int tid = threadIdx.x;

    __shared__ float s_inv[NREG];

    const float* __restrict__ base = g_M + b * NREG * 512 + ch;   // prelude

    asm volatile("griddepcontrol.wait;" ::: "memory");

    // issue all 14 independent g_M loads first (overlap with norm chain below)
    float v[NREG];
#pragma unroll
    for (int r = 0; r < NREG; ++r)
        v[r] = base[r * 512];

    if (tid < NREG)
        s_inv[tid] = 1.0f / (sqrtf(g_SS[b * NREG + tid]) + 1e-6f);
    __syncthreads();
    if (tid < NREG)                  // re-zero off the critical path
        g_SS[b * NREG + tid] = 0.0f;

    float acc = 2.0f * v[0] * s_inv[0];     // (R0,R0) weight 2
#pragma unroll
    for (int r = 1; r < NREG; ++r)
        acc += v[r] * s_inv[r];
    out[b * 512 + ch] = acc;
}

extern "C" void kernel_launch(void* const* d_in, const int* in_sizes, int n_in,
                              void* d_out, int out_size) {
    const float* x = (const float*)d_in[0];
    float* out = (float*)d_out;

    rmac_stage1<<<8192, 128>>>(x);

    cudaLaunchConfig_t cfg = {};
    cfg.gridDim  = dim3(128, 1, 1);
    cfg.blockDim = dim3(256, 1, 1);
    cfg.dynamicSmemBytes = 0;
    cfg.stream = 0;
    cudaLaunchAttribute attr[1];
    attr[0].id = cudaLaunchAttributeProgrammaticStreamSerialization;
    attr[0].val.programmaticStreamSerializationAllowed = 1;
    cfg.attrs = attr;
    cfg.numAttrs = 1;
    cudaLaunchKernelEx(&cfg, rmac_stage2, out);
}